// round 13
// baseline (speedup 1.0000x reference)
#include <cuda_runtime.h>
#include <cuda_fp16.h>
#include <math.h>
#include <stdint.h>

// ===========================================================================
// COR_Critic — single-pass fp16 mma.sync (HMMA) + ldmatrix + cp.async.
// R11 = R10 with the pipeline under-wait fixed: tile kt must be COMPLETE
// before compute -> wait_group 1 (only tile kt+1 may stay pending).
// Paired-B ldsm4: 6 LDSM per warp k-step (2xA ldsm4 + 4xB ldsm4) vs 10.
//   sa  = concat(state, action) -> [B,32] (padded to 64)
//   X1  = tanh(sa @ A1 + b1) * gate1      -> [B,1024]
//   X2  = tanh(X1 @ A2 + b2) * gate2      -> [B,1024]
//   H1p = X2 @ Wq1 + bq1 ; H1 = relu(LN(H1p))  (fp16)
//   H2p = H1 @ Wq2 + bq2 ; out = relu(LN(H2p)) @ Wq3 + bq3
// ===========================================================================

#define NB 131072
using fp16 = __half;

// ---------------- device scratch (static, no allocation) -------------------
__device__ fp16 g_SAf[(size_t)NB * 64];
__device__ fp16 g_W1t[1024 * 64];
__device__ fp16 g_W2t[1024 * 1024];
__device__ fp16 g_Q1t[256 * 1024];
__device__ fp16 g_Q2t[128 * 256];
__device__ fp16 g_X1f[(size_t)NB * 1024];
__device__ fp16 g_X2f[(size_t)NB * 1024];
__device__ float g_H1p[(size_t)NB * 256];
__device__ fp16 g_H1f[(size_t)NB * 256];
__device__ float g_H2p[(size_t)NB * 128];
__device__ float g_GATE[64];

// ---------------- PTX helpers ----------------------------------------------
__device__ __forceinline__ uint32_t smem_u32(const void* p) {
    uint32_t a;
    asm("{ .reg .u64 t; cvta.to.shared.u64 t, %1; cvt.u32.u64 %0, t; }"
        : "=r"(a) : "l"(p));
    return a;
}
__device__ __forceinline__ void cp16(uint32_t s, const void* g) {
    asm volatile("cp.async.cg.shared.global [%0], [%1], 16;" :: "r"(s), "l"(g));
}
#define CP_COMMIT() asm volatile("cp.async.commit_group;" ::: "memory")
__device__ __forceinline__ void ldsm4(uint32_t* r, uint32_t a) {
    asm volatile("ldmatrix.sync.aligned.m8n8.x4.shared.b16 {%0,%1,%2,%3}, [%4];"
                 : "=r"(r[0]), "=r"(r[1]), "=r"(r[2]), "=r"(r[3]) : "r"(a));
}
__device__ __forceinline__ void mma16816(float* d, const uint32_t* a, const uint32_t* b) {
    asm volatile(
        "mma.sync.aligned.m16n8k16.row.col.f32.f16.f16.f32 "
        "{%0,%1,%2,%3}, {%4,%5,%6,%7}, {%8,%9}, {%0,%1,%2,%3};"
        : "+f"(d[0]), "+f"(d[1]), "+f"(d[2]), "+f"(d[3])
        : "r"(a[0]), "r"(a[1]), "r"(a[2]), "r"(a[3]), "r"(b[0]), "r"(b[1]));
}

// ---------------- prep kernels ---------------------------------------------
__global__ void prep_saf(const float* __restrict__ st, const float* __restrict__ ac,
                         fp16* __restrict__ o, int M) {
    int idx = blockIdx.x * blockDim.x + threadIdx.x;
    if (idx >= M * 64) return;
    int b = idx >> 6, j = idx & 63;
    float v = 0.f;
    if (j < 24) v = st[b * 24 + j];
    else if (j < 32) v = ac[b * 8 + (j - 24)];
    o[idx] = __float2half_rn(v);
}
__global__ void prep_w1t(const float* __restrict__ W, fp16* __restrict__ h) {
    int idx = blockIdx.x * blockDim.x + threadIdx.x;
    if (idx >= 1024 * 64) return;
    int n = idx >> 6, k = idx & 63;
    float v = (k < 32) ? W[((size_t)((n >> 5) * 32 + k)) * 32 + (n & 31)] : 0.f;
    h[idx] = __float2half_rn(v);
}
__global__ void prep_w2t(const float* __restrict__ W, fp16* __restrict__ h) {
    int idx = blockIdx.x * blockDim.x + threadIdx.x;
    if (idx >= 1024 * 1024) return;
    int n = idx >> 10, k = idx & 1023;
    h[idx] = __float2half_rn(W[((size_t)(n >> 5) * 1024 + k) * 32 + (n & 31)]);
}
__global__ void prep_wt(const float* __restrict__ W, fp16* __restrict__ h, int Nn, int K) {
    int idx = blockIdx.x * blockDim.x + threadIdx.x;
    if (idx >= Nn * K) return;
    int n = idx / K, k = idx - n * K;
    h[idx] = __float2half_rn(W[(size_t)k * Nn + n]);
}
__global__ void prep_gates(const float* __restrict__ g1, const float* __restrict__ g2,
                           float* __restrict__ out) {
    int t = threadIdx.x;
    if (t < 32)      out[t] = 1.0f / (1.0f + expf(-g1[t]));
    else if (t < 64) out[t] = 1.0f / (1.0f + expf(-g2[t - 32]));
}

// ---------------- HMMA GEMM -------------------------------------------------
// C[M,N] = Af[M,K] @ W[N,K]^T, fp32 acc in regs.
// BM=128, BN=128, BK=64, 8 warps (4m x 2n), warp tile 32x64.
// 3-stage cp.async pipeline; B fragments via paired ldsm4 (2 n-tiles each).
// EPI 0: tanh(acc+bias)*gate -> fp16.   EPI 1: acc+bias -> fp32.
template <int EPI>
__global__ void __launch_bounds__(256)
mma_gemm(const fp16* __restrict__ Af, const fp16* __restrict__ Bw,
         int K, int ldC,
         const float* __restrict__ bias, const float* __restrict__ gate,
         float* __restrict__ Cf, fp16* __restrict__ Ch) {
    constexpr int TILE = 128 * 64 * 2;   // 16 KB per operand tile
    constexpr int BUF = 2 * TILE;        // Af | Bw per stage
    constexpr int NSTG = 3;

    extern __shared__ char dsm[];
    const uint32_t sb = (smem_u32(dsm) + 1023) & ~1023u;

    const int tid = threadIdx.x;
    const int wid = tid >> 5, lane = tid & 31;
    const int wm = wid >> 1, wn = wid & 1;
    const size_t bm = (size_t)blockIdx.y * 128;
    const int bn = blockIdx.x * 128;
    const int nk = K >> 6;

    auto load_tile = [&](int kt, int buf) {
        const uint32_t base = sb + buf * BUF;
#pragma unroll
        for (int i = 0; i < 4; i++) {
            const int c = tid + 256 * i;
            const int row = c >> 3;
            const uint32_t sw = (uint32_t)(row * 128) +
                                (uint32_t)(((c & 7) << 4) ^ ((row & 7) << 4));
            const size_t kofs = (size_t)kt * 64 + ((c & 7) << 3);
            cp16(base + sw, Af + (bm + row) * (size_t)K + kofs);
            cp16(base + TILE + sw, Bw + (size_t)(bn + row) * K + kofs);
        }
    };

    // A ldmatrix addresses: 2 m-tiles, ldsm4 each
    const int r15 = lane & 15, halfA = lane >> 4;
    int pA[2], xA[2];
#pragma unroll
    for (int mt = 0; mt < 2; mt++) {
        const int rowA = wm * 32 + mt * 16 + r15;
        pA[mt] = rowA * 128;
        xA[mt] = (rowA & 7) << 4;
    }
    // B paired ldsm4: one instruction covers n-tiles 2p and 2p+1.
    // address lanes 0-7: (2p, khalf0) -> r0 | 8-15: (2p, khalf1) -> r1
    //              16-23: (2p+1, khalf0) -> r2 | 24-31: (2p+1, khalf1) -> r3
    const int l8 = lane & 7;
    const int selN = lane >> 4;
    const int selK = (lane >> 3) & 1;
    const int xB = l8 << 4;
    int pB[4];
#pragma unroll
    for (int p = 0; p < 4; p++)
        pB[p] = (wn * 64 + p * 16 + selN * 8 + l8) * 128;

    float acc[2][8][4];
#pragma unroll
    for (int mt = 0; mt < 2; mt++)
#pragma unroll
        for (int nt = 0; nt < 8; nt++)
#pragma unroll
            for (int q = 0; q < 4; q++) acc[mt][nt][q] = 0.f;

    // prologue: 2 tiles in flight
    load_tile(0, 0);
    CP_COMMIT();
    if (nk > 1) { load_tile(1, 1); CP_COMMIT(); }

    for (int kt = 0; kt < nk; kt++) {
        const int buf = kt % NSTG;
        // tile kt must be COMPLETE; only tile kt+1 may remain pending.
        if (kt + 1 < nk) { asm volatile("cp.async.wait_group 1;" ::: "memory"); }
        else             { asm volatile("cp.async.wait_group 0;" ::: "memory"); }
        __syncthreads();

        const uint32_t tA = sb + buf * BUF;
        const uint32_t tB = tA + TILE;
#pragma unroll
        for (int ks = 0; ks < 4; ks++) {
            const int kbA = ks * 32 + 16 * halfA;
            const int kbB = ks * 32 + 16 * selK;
            uint32_t a[2][4], bfr[4][4];
#pragma unroll
            for (int mt = 0; mt < 2; mt++)
                ldsm4(a[mt], tA + pA[mt] + (kbA ^ xA[mt]));
#pragma unroll
            for (int p = 0; p < 4; p++)
                ldsm4(bfr[p], tB + pB[p] + (kbB ^ xB));
#pragma unroll
            for (int mt = 0; mt < 2; mt++)
#pragma unroll
                for (int p = 0; p < 4; p++) {
                    mma16816(acc[mt][2 * p + 0], a[mt], &bfr[p][0]);
                    mma16816(acc[mt][2 * p + 1], a[mt], &bfr[p][2]);
                }
        }
        // issue load for kt+2 AFTER compute: its buffer was last read at
        // kt-1, and the syncthreads above guarantees all warps passed it.
        if (kt + 2 < nk) { load_tile(kt + 2, (kt + 2) % NSTG); CP_COMMIT(); }
    }

    // ---- epilogue (acc in regs) ----
    const int gid = lane >> 2, qd = lane & 3;
#pragma unroll
    for (int nt = 0; nt < 8; nt++) {
        const int c = bn + wn * 64 + nt * 8 + qd * 2;
        const float b0 = bias[c], b1 = bias[c + 1];
        float gv = 0.f;
        if (EPI == 0) gv = gate[c >> 5];
#pragma unroll
        for (int mt = 0; mt < 2; mt++) {
            const size_t r0 = bm + wm * 32 + mt * 16 + gid;
            if (EPI == 0) {
#pragma unroll
                for (int half = 0; half < 2; half++) {
                    const size_t row = r0 + 8 * half;
                    const float v0 = tanhf(acc[mt][nt][2 * half + 0] + b0) * gv;
                    const float v1 = tanhf(acc[mt][nt][2 * half + 1] + b1) * gv;
                    *(uint32_t*)(Ch + row * (size_t)ldC + c) =
                        ((uint32_t)__half_as_ushort(__float2half_rn(v1)) << 16) |
                        __half_as_ushort(__float2half_rn(v0));
                }
            } else {
#pragma unroll
                for (int half = 0; half < 2; half++) {
                    const size_t row = r0 + 8 * half;
                    float2 o;
                    o.x = acc[mt][nt][2 * half + 0] + b0;
                    o.y = acc[mt][nt][2 * half + 1] + b1;
                    *(float2*)(Cf + row * (size_t)ldC + c) = o;
                }
            }
        }
    }
}

// ---------------- LN + ReLU -> fp16 (one warp per row) ---------------------
template <int D>
__global__ void ln_relu_f16(const float* __restrict__ X, const float* __restrict__ gm,
                            const float* __restrict__ bt, fp16* __restrict__ Y, int M) {
    const int row = blockIdx.x * (blockDim.x >> 5) + (threadIdx.x >> 5);
    if (row >= M) return;
    const int lane = threadIdx.x & 31;
    constexpr int PT = D / 32;
    float v[PT];
    const float* rp = X + (size_t)row * D;
    float s = 0.f;
#pragma unroll
    for (int i = 0; i < PT; i++) { v[i] = rp[lane + 32 * i]; s += v[i]; }
#pragma unroll
    for (int o = 16; o; o >>= 1) s += __shfl_xor_sync(0xffffffffu, s, o);
    const float mu = s * (1.0f / D);
    float vs = 0.f;
#pragma unroll
    for (int i = 0; i < PT; i++) { float d = v[i] - mu; vs += d * d; }
#pragma unroll
    for (int o = 16; o; o >>= 1) vs += __shfl_xor_sync(0xffffffffu, vs, o);
    const float inv = rsqrtf(vs * (1.0f / D) + 1e-5f);
#pragma unroll
    for (int i = 0; i < PT; i++) {
        float y = (v[i] - mu) * inv * gm[lane + 32 * i] + bt[lane + 32 * i];
        Y[(size_t)row * D + lane + 32 * i] = __float2half_rn(fmaxf(y, 0.f));
    }
}

// ---------------- fused LN2 + ReLU + dot (one warp per row) ----------------
__global__ void ln2_dot(const float* __restrict__ X, const float* __restrict__ gm,
                        const float* __restrict__ bt, const float* __restrict__ w,
                        const float* __restrict__ b, float* __restrict__ out, int M) {
    const int row = blockIdx.x * (blockDim.x >> 5) + (threadIdx.x >> 5);
    if (row >= M) return;
    const int lane = threadIdx.x & 31;
    float v[4];
    const float* rp = X + (size_t)row * 128;
    float s = 0.f;
#pragma unroll
    for (int i = 0; i < 4; i++) { v[i] = rp[lane + 32 * i]; s += v[i]; }
#pragma unroll
    for (int o = 16; o; o >>= 1) s += __shfl_xor_sync(0xffffffffu, s, o);
    const float mu = s * (1.0f / 128.0f);
    float vs = 0.f;
#pragma unroll
    for (int i = 0; i < 4; i++) { float d = v[i] - mu; vs += d * d; }
#pragma unroll
    for (int o = 16; o; o >>= 1) vs += __shfl_xor_sync(0xffffffffu, vs, o);
    const float inv = rsqrtf(vs * (1.0f / 128.0f) + 1e-5f);
    float acc = 0.f;
#pragma unroll
    for (int i = 0; i < 4; i++) {
        float y = (v[i] - mu) * inv * gm[lane + 32 * i] + bt[lane + 32 * i];
        y = fmaxf(y, 0.f);
        acc = fmaf(y, w[lane + 32 * i], acc);
    }
#pragma unroll
    for (int o = 16; o; o >>= 1) acc += __shfl_xor_sync(0xffffffffu, acc, o);
    if (lane == 0) out[row] = acc + b[0];
}

// ---------------- launch ----------------------------------------------------
extern "C" void kernel_launch(void* const* d_in, const int* in_sizes, int n_in,
                              void* d_out, int out_size) {
    const float* state = (const float*)d_in[0];
    const float* action = (const float*)d_in[1];
    const float* W1 = (const float*)d_in[2];
    const float* b1 = (const float*)d_in[3];
    const float* g1 = (const float*)d_in[4];
    const float* W2 = (const float*)d_in[5];
    const float* b2 = (const float*)d_in[6];
    const float* g2 = (const float*)d_in[7];
    const float* Wq1 = (const float*)d_in[8];
    const float* bq1 = (const float*)d_in[9];
    const float* ln1g = (const float*)d_in[10];
    const float* ln1b = (const float*)d_in[11];
    const float* Wq2 = (const float*)d_in[12];
    const float* bq2 = (const float*)d_in[13];
    const float* ln2g = (const float*)d_in[14];
    const float* ln2b = (const float*)d_in[15];
    const float* Wq3 = (const float*)d_in[16];
    const float* bq3 = (const float*)d_in[17];
    float* out = (float*)d_out;

    const int M = in_sizes[0] / 24;
    if (M <= 0) return;

    fp16 *saf, *w1t, *w2t, *q1t, *q2t, *x1f, *x2f, *h1f;
    float *h1p, *h2p, *gt;
    cudaGetSymbolAddress((void**)&saf, g_SAf);
    cudaGetSymbolAddress((void**)&w1t, g_W1t);
    cudaGetSymbolAddress((void**)&w2t, g_W2t);
    cudaGetSymbolAddress((void**)&q1t, g_Q1t);
    cudaGetSymbolAddress((void**)&q2t, g_Q2t);
    cudaGetSymbolAddress((void**)&x1f, g_X1f);
    cudaGetSymbolAddress((void**)&x2f, g_X2f);
    cudaGetSymbolAddress((void**)&h1f, g_H1f);
    cudaGetSymbolAddress((void**)&h1p, g_H1p);
    cudaGetSymbolAddress((void**)&h2p, g_H2p);
    cudaGetSymbolAddress((void**)&gt, g_GATE);

    const int SMEM = 3 * (2 * 128 * 64 * 2) + 1024;   // 99328 B (3 stages)
    cudaFuncSetAttribute(mma_gemm<0>, cudaFuncAttributeMaxDynamicSharedMemorySize, SMEM);
    cudaFuncSetAttribute(mma_gemm<1>, cudaFuncAttributeMaxDynamicSharedMemorySize, SMEM);

    prep_saf<<<(M * 64 + 255) / 256, 256>>>(state, action, saf, M);
    prep_w1t<<<(1024 * 64 + 255) / 256, 256>>>(W1, w1t);
    prep_w2t<<<(1024 * 1024 + 255) / 256, 256>>>(W2, w2t);
    prep_wt<<<(256 * 1024 + 255) / 256, 256>>>(Wq1, q1t, 256, 1024);
    prep_wt<<<(128 * 256 + 255) / 256, 256>>>(Wq2, q2t, 128, 256);
    prep_gates<<<1, 64>>>(g1, g2, gt);

    const int MB = M / 128;

    // G0: [M,64pad] @ [1024,64]^T -> X1 (tanh * gate1)
    mma_gemm<0><<<dim3(8, MB), 256, SMEM>>>(saf, w1t, 64, 1024, b1, gt, nullptr, x1f);
    // G1: [M,1024] @ [1024,1024]^T -> X2 (tanh * gate2)   (dominant)
    mma_gemm<0><<<dim3(8, MB), 256, SMEM>>>(x1f, w2t, 1024, 1024, b2, gt + 32, nullptr, x2f);
    // G2: [M,1024] @ [256,1024]^T -> H1p (+bq1)
    mma_gemm<1><<<dim3(2, MB), 256, SMEM>>>(x2f, q1t, 1024, 256, bq1, nullptr, h1p, nullptr);
    ln_relu_f16<256><<<(M + 7) / 8, 256>>>(h1p, ln1g, ln1b, h1f, M);
    // G3: [M,256] @ [128,256]^T -> H2p (+bq2)
    mma_gemm<1><<<dim3(1, MB), 256, SMEM>>>(h1f, q2t, 256, 128, bq2, nullptr, h2p, nullptr);
    ln2_dot<<<(M + 7) / 8, 256>>>(h2p, ln2g, ln2b, Wq3, bq3, out, M);
}

// round 14
// speedup vs baseline: 1.1796x; 1.1796x over previous
#include <cuda_runtime.h>
#include <cuda_fp16.h>
#include <math.h>
#include <stdint.h>

// ===========================================================================
// COR_Critic — single-pass fp16 mma.sync (HMMA) + ldmatrix + cp.async.
// R14 = R8 core (2-stage pipeline, 66KB smem -> 3 CTAs/SM, ldsm2 B frags)
//       + G3 fused epilogue (LN2 + ReLU + dot in-kernel; H2p never leaves SM).
//   sa  = concat(state, action) -> [B,32] (padded to 64)
//   X1  = tanh(sa @ A1 + b1) * gate1      -> [B,1024]
//   X2  = tanh(X1 @ A2 + b2) * gate2      -> [B,1024]
//   H1p = X2 @ Wq1 + bq1 ; H1 = relu(LN(H1p))  (fp16)
//   out = relu(LN(H1 @ Wq2 + bq2)) @ Wq3 + bq3   (one fused kernel)
// ===========================================================================

#define NB 131072
using fp16 = __half;

// ---------------- device scratch (static, no allocation) -------------------
__device__ fp16 g_SAf[(size_t)NB * 64];
__device__ fp16 g_W1t[1024 * 64];
__device__ fp16 g_W2t[1024 * 1024];
__device__ fp16 g_Q1t[256 * 1024];
__device__ fp16 g_Q2t[128 * 256];
__device__ fp16 g_X1f[(size_t)NB * 1024];
__device__ fp16 g_X2f[(size_t)NB * 1024];
__device__ float g_H1p[(size_t)NB * 256];
__device__ fp16 g_H1f[(size_t)NB * 256];
__device__ float g_GATE[64];

// ---------------- PTX helpers ----------------------------------------------
__device__ __forceinline__ uint32_t smem_u32(const void* p) {
    uint32_t a;
    asm("{ .reg .u64 t; cvta.to.shared.u64 t, %1; cvt.u32.u64 %0, t; }"
        : "=r"(a) : "l"(p));
    return a;
}
__device__ __forceinline__ void cp16(uint32_t s, const void* g) {
    asm volatile("cp.async.cg.shared.global [%0], [%1], 16;" :: "r"(s), "l"(g));
}
#define CP_COMMIT() asm volatile("cp.async.commit_group;" ::: "memory")
__device__ __forceinline__ void ldsm4(uint32_t* r, uint32_t a) {
    asm volatile("ldmatrix.sync.aligned.m8n8.x4.shared.b16 {%0,%1,%2,%3}, [%4];"
                 : "=r"(r[0]), "=r"(r[1]), "=r"(r[2]), "=r"(r[3]) : "r"(a));
}
__device__ __forceinline__ void ldsm2(uint32_t* r, uint32_t a) {
    asm volatile("ldmatrix.sync.aligned.m8n8.x2.shared.b16 {%0,%1}, [%2];"
                 : "=r"(r[0]), "=r"(r[1]) : "r"(a));
}
__device__ __forceinline__ void mma16816(float* d, const uint32_t* a, const uint32_t* b) {
    asm volatile(
        "mma.sync.aligned.m16n8k16.row.col.f32.f16.f16.f32 "
        "{%0,%1,%2,%3}, {%4,%5,%6,%7}, {%8,%9}, {%0,%1,%2,%3};"
        : "+f"(d[0]), "+f"(d[1]), "+f"(d[2]), "+f"(d[3])
        : "r"(a[0]), "r"(a[1]), "r"(a[2]), "r"(a[3]), "r"(b[0]), "r"(b[1]));
}

// ---------------- prep kernels ---------------------------------------------
__global__ void prep_saf(const float* __restrict__ st, const float* __restrict__ ac,
                         fp16* __restrict__ o, int M) {
    int idx = blockIdx.x * blockDim.x + threadIdx.x;
    if (idx >= M * 64) return;
    int b = idx >> 6, j = idx & 63;
    float v = 0.f;
    if (j < 24) v = st[b * 24 + j];
    else if (j < 32) v = ac[b * 8 + (j - 24)];
    o[idx] = __float2half_rn(v);
}
__global__ void prep_w1t(const float* __restrict__ W, fp16* __restrict__ h) {
    int idx = blockIdx.x * blockDim.x + threadIdx.x;
    if (idx >= 1024 * 64) return;
    int n = idx >> 6, k = idx & 63;
    float v = (k < 32) ? W[((size_t)((n >> 5) * 32 + k)) * 32 + (n & 31)] : 0.f;
    h[idx] = __float2half_rn(v);
}
__global__ void prep_w2t(const float* __restrict__ W, fp16* __restrict__ h) {
    int idx = blockIdx.x * blockDim.x + threadIdx.x;
    if (idx >= 1024 * 1024) return;
    int n = idx >> 10, k = idx & 1023;
    h[idx] = __float2half_rn(W[((size_t)(n >> 5) * 1024 + k) * 32 + (n & 31)]);
}
__global__ void prep_wt(const float* __restrict__ W, fp16* __restrict__ h, int Nn, int K) {
    int idx = blockIdx.x * blockDim.x + threadIdx.x;
    if (idx >= Nn * K) return;
    int n = idx / K, k = idx - n * K;
    h[idx] = __float2half_rn(W[(size_t)k * Nn + n]);
}
__global__ void prep_gates(const float* __restrict__ g1, const float* __restrict__ g2,
                           float* __restrict__ out) {
    int t = threadIdx.x;
    if (t < 32)      out[t] = 1.0f / (1.0f + expf(-g1[t]));
    else if (t < 64) out[t] = 1.0f / (1.0f + expf(-g2[t - 32]));
}

// ---------------- HMMA GEMM (R8-proven core) --------------------------------
// C[M,N] = Af[M,K] @ W[N,K]^T, fp32 acc in regs.
// BM=128, BN=128, BK=64, 8 warps (4m x 2n), warp tile 32x64, 2-stage.
// EPI 0: tanh(acc+bias)*gate -> fp16.   EPI 1: acc+bias -> fp32.
template <int EPI>
__global__ void __launch_bounds__(256)
mma_gemm(const fp16* __restrict__ Af, const fp16* __restrict__ Bw,
         int K, int ldC,
         const float* __restrict__ bias, const float* __restrict__ gate,
         float* __restrict__ Cf, fp16* __restrict__ Ch) {
    constexpr int TILE = 128 * 64 * 2;   // 16 KB per operand tile
    constexpr int BUF = 2 * TILE;        // Af | Bw

    extern __shared__ char dsm[];
    const uint32_t sb = (smem_u32(dsm) + 1023) & ~1023u;

    const int tid = threadIdx.x;
    const int wid = tid >> 5, lane = tid & 31;
    const int wm = wid >> 1, wn = wid & 1;
    const size_t bm = (size_t)blockIdx.y * 128;
    const int bn = blockIdx.x * 128;
    const int nk = K >> 6;

    auto load_tile = [&](int kt, int buf) {
        const uint32_t base = sb + buf * BUF;
#pragma unroll
        for (int i = 0; i < 4; i++) {
            const int c = tid + 256 * i;
            const int row = c >> 3;
            const uint32_t sw = (uint32_t)(row * 128) +
                                (uint32_t)(((c & 7) << 4) ^ ((row & 7) << 4));
            const size_t kofs = (size_t)kt * 64 + ((c & 7) << 3);
            cp16(base + sw, Af + (bm + row) * (size_t)K + kofs);
            cp16(base + TILE + sw, Bw + (size_t)(bn + row) * K + kofs);
        }
    };

    const int r15 = lane & 15, halfA = lane >> 4;
    int pA[2], xA[2];
#pragma unroll
    for (int mt = 0; mt < 2; mt++) {
        const int rowA = wm * 32 + mt * 16 + r15;
        pA[mt] = rowA * 128;
        xA[mt] = (rowA & 7) << 4;
    }
    const int l8 = lane & 7, halfB = (lane & 15) >> 3;
    const int xB = l8 << 4;
    int pB[8];
#pragma unroll
    for (int nt = 0; nt < 8; nt++) pB[nt] = (wn * 64 + nt * 8 + l8) * 128;

    float acc[2][8][4];
#pragma unroll
    for (int mt = 0; mt < 2; mt++)
#pragma unroll
        for (int nt = 0; nt < 8; nt++)
#pragma unroll
            for (int q = 0; q < 4; q++) acc[mt][nt][q] = 0.f;

    load_tile(0, 0);
    CP_COMMIT();

    for (int kt = 0; kt < nk; kt++) {
        const int buf = kt & 1;
        if (kt + 1 < nk) {
            load_tile(kt + 1, buf ^ 1);
            CP_COMMIT();
            asm volatile("cp.async.wait_group 1;" ::: "memory");
        } else {
            asm volatile("cp.async.wait_group 0;" ::: "memory");
        }
        __syncthreads();

        const uint32_t tA = sb + buf * BUF;
        const uint32_t tB = tA + TILE;
#pragma unroll
        for (int ks = 0; ks < 4; ks++) {
            const int kbA = ks * 32 + 16 * halfA;
            const int kbB = ks * 32 + 16 * halfB;
            uint32_t a[2][4], bfr[8][2];
#pragma unroll
            for (int mt = 0; mt < 2; mt++)
                ldsm4(a[mt], tA + pA[mt] + (kbA ^ xA[mt]));
#pragma unroll
            for (int nt = 0; nt < 8; nt++)
                ldsm2(bfr[nt], tB + pB[nt] + (kbB ^ xB));
#pragma unroll
            for (int mt = 0; mt < 2; mt++)
#pragma unroll
                for (int nt = 0; nt < 8; nt++)
                    mma16816(acc[mt][nt], a[mt], bfr[nt]);
        }
        __syncthreads();
    }

    const int gid = lane >> 2, qd = lane & 3;
#pragma unroll
    for (int nt = 0; nt < 8; nt++) {
        const int c = bn + wn * 64 + nt * 8 + qd * 2;
        const float b0 = bias[c], b1 = bias[c + 1];
        float gv = 0.f;
        if (EPI == 0) gv = gate[c >> 5];
#pragma unroll
        for (int mt = 0; mt < 2; mt++) {
            const size_t r0 = bm + wm * 32 + mt * 16 + gid;
            if (EPI == 0) {
#pragma unroll
                for (int half = 0; half < 2; half++) {
                    const size_t row = r0 + 8 * half;
                    const float v0 = tanhf(acc[mt][nt][2 * half + 0] + b0) * gv;
                    const float v1 = tanhf(acc[mt][nt][2 * half + 1] + b1) * gv;
                    *(uint32_t*)(Ch + row * (size_t)ldC + c) =
                        ((uint32_t)__half_as_ushort(__float2half_rn(v1)) << 16) |
                        __half_as_ushort(__float2half_rn(v0));
                }
            } else {
#pragma unroll
                for (int half = 0; half < 2; half++) {
                    const size_t row = r0 + 8 * half;
                    float2 o;
                    o.x = acc[mt][nt][2 * half + 0] + b0;
                    o.y = acc[mt][nt][2 * half + 1] + b1;
                    *(float2*)(Cf + row * (size_t)ldC + c) = o;
                }
            }
        }
    }
}

// ---------------- G3 fused: GEMM + LN2 + ReLU + dot -------------------------
// H1[128-row block, 256] @ Q2[128,256]^T + bq2 -> pre-LN in SMEM ->
// LN+ReLU+dot(Wq3) -> out.  Same mainloop as mma_gemm (K=256, BN=128, bn=0).
__global__ void __launch_bounds__(256)
g3_fused(const fp16* __restrict__ Af, const fp16* __restrict__ Bw,
         const float* __restrict__ bq2,
         const float* __restrict__ ln2g, const float* __restrict__ ln2b,
         const float* __restrict__ wq3, const float* __restrict__ bq3,
         float* __restrict__ out) {
    constexpr int TILE = 128 * 64 * 2;
    constexpr int BUF = 2 * TILE;
    constexpr int K = 256, nk = 4;
    constexpr int PS = 132;             // fp32 row stride for pre-LN staging

    extern __shared__ char dsm[];
    const uint32_t sb = (smem_u32(dsm) + 1023) & ~1023u;

    const int tid = threadIdx.x;
    const int wid = tid >> 5, lane = tid & 31;
    const int wm = wid >> 1, wn = wid & 1;
    const size_t bm = (size_t)blockIdx.x * 128;

    auto load_tile = [&](int kt, int buf) {
        const uint32_t base = sb + buf * BUF;
#pragma unroll
        for (int i = 0; i < 4; i++) {
            const int c = tid + 256 * i;
            const int row = c >> 3;
            const uint32_t sw = (uint32_t)(row * 128) +
                                (uint32_t)(((c & 7) << 4) ^ ((row & 7) << 4));
            const size_t kofs = (size_t)kt * 64 + ((c & 7) << 3);
            cp16(base + sw, Af + (bm + row) * (size_t)K + kofs);
            cp16(base + TILE + sw, Bw + (size_t)row * K + kofs);
        }
    };

    const int r15 = lane & 15, halfA = lane >> 4;
    int pA[2], xA[2];
#pragma unroll
    for (int mt = 0; mt < 2; mt++) {
        const int rowA = wm * 32 + mt * 16 + r15;
        pA[mt] = rowA * 128;
        xA[mt] = (rowA & 7) << 4;
    }
    const int l8 = lane & 7, halfB = (lane & 15) >> 3;
    const int xB = l8 << 4;
    int pB[8];
#pragma unroll
    for (int nt = 0; nt < 8; nt++) pB[nt] = (wn * 64 + nt * 8 + l8) * 128;

    float acc[2][8][4];
#pragma unroll
    for (int mt = 0; mt < 2; mt++)
#pragma unroll
        for (int nt = 0; nt < 8; nt++)
#pragma unroll
            for (int q = 0; q < 4; q++) acc[mt][nt][q] = 0.f;

    load_tile(0, 0);
    CP_COMMIT();

    for (int kt = 0; kt < nk; kt++) {
        const int buf = kt & 1;
        if (kt + 1 < nk) {
            load_tile(kt + 1, buf ^ 1);
            CP_COMMIT();
            asm volatile("cp.async.wait_group 1;" ::: "memory");
        } else {
            asm volatile("cp.async.wait_group 0;" ::: "memory");
        }
        __syncthreads();

        const uint32_t tA = sb + buf * BUF;
        const uint32_t tB = tA + TILE;
#pragma unroll
        for (int ks = 0; ks < 4; ks++) {
            const int kbA = ks * 32 + 16 * halfA;
            const int kbB = ks * 32 + 16 * halfB;
            uint32_t a[2][4], bfr[8][2];
#pragma unroll
            for (int mt = 0; mt < 2; mt++)
                ldsm4(a[mt], tA + pA[mt] + (kbA ^ xA[mt]));
#pragma unroll
            for (int nt = 0; nt < 8; nt++)
                ldsm2(bfr[nt], tB + pB[nt] + (kbB ^ xB));
#pragma unroll
            for (int mt = 0; mt < 2; mt++)
#pragma unroll
                for (int nt = 0; nt < 8; nt++)
                    mma16816(acc[mt][nt], a[mt], bfr[nt]);
        }
        __syncthreads();   // also guards smem reuse by the staging below
    }

    // ---- stage pre-LN fp32 to SMEM ----
    float* const spre = (float*)(dsm + (sb - smem_u32(dsm)));
    const int gid = lane >> 2, qd = lane & 3;
#pragma unroll
    for (int nt = 0; nt < 8; nt++) {
        const int c = wn * 64 + nt * 8 + qd * 2;
        const float b0 = bq2[c], b1 = bq2[c + 1];
#pragma unroll
        for (int mt = 0; mt < 2; mt++) {
            const int r0 = wm * 32 + mt * 16 + gid;
#pragma unroll
            for (int half = 0; half < 2; half++) {
                const int row = r0 + 8 * half;
                spre[row * PS + c]     = acc[mt][nt][2 * half + 0] + b0;
                spre[row * PS + c + 1] = acc[mt][nt][2 * half + 1] + b1;
            }
        }
    }
    __syncthreads();

    // ---- LN2 + ReLU + dot(Wq3) -> out ----
    const float bq3v = bq3[0];
#pragma unroll
    for (int j = 0; j < 16; j++) {
        const int row = wid * 16 + j;
        float v[4];
        float s = 0.f;
#pragma unroll
        for (int i = 0; i < 4; i++) { v[i] = spre[row * PS + lane + 32 * i]; s += v[i]; }
#pragma unroll
        for (int o = 16; o; o >>= 1) s += __shfl_xor_sync(0xffffffffu, s, o);
        const float mu = s * (1.0f / 128.0f);
        float vs = 0.f;
#pragma unroll
        for (int i = 0; i < 4; i++) { float d = v[i] - mu; vs += d * d; }
#pragma unroll
        for (int o = 16; o; o >>= 1) vs += __shfl_xor_sync(0xffffffffu, vs, o);
        const float inv = rsqrtf(vs * (1.0f / 128.0f) + 1e-5f);
        float dot = 0.f;
#pragma unroll
        for (int i = 0; i < 4; i++) {
            const int c = lane + 32 * i;
            float y = (v[i] - mu) * inv * ln2g[c] + ln2b[c];
            y = fmaxf(y, 0.f);
            dot = fmaf(y, wq3[c], dot);
        }
#pragma unroll
        for (int o = 16; o; o >>= 1) dot += __shfl_xor_sync(0xffffffffu, dot, o);
        if (lane == 0) out[bm + row] = dot + bq3v;
    }
}

// ---------------- LN + ReLU -> fp16 (one warp per row) ---------------------
template <int D>
__global__ void ln_relu_f16(const float* __restrict__ X, const float* __restrict__ gm,
                            const float* __restrict__ bt, fp16* __restrict__ Y, int M) {
    const int row = blockIdx.x * (blockDim.x >> 5) + (threadIdx.x >> 5);
    if (row >= M) return;
    const int lane = threadIdx.x & 31;
    constexpr int PT = D / 32;
    float v[PT];
    const float* rp = X + (size_t)row * D;
    float s = 0.f;
#pragma unroll
    for (int i = 0; i < PT; i++) { v[i] = rp[lane + 32 * i]; s += v[i]; }
#pragma unroll
    for (int o = 16; o; o >>= 1) s += __shfl_xor_sync(0xffffffffu, s, o);
    const float mu = s * (1.0f / D);
    float vs = 0.f;
#pragma unroll
    for (int i = 0; i < PT; i++) { float d = v[i] - mu; vs += d * d; }
#pragma unroll
    for (int o = 16; o; o >>= 1) vs += __shfl_xor_sync(0xffffffffu, vs, o);
    const float inv = rsqrtf(vs * (1.0f / D) + 1e-5f);
#pragma unroll
    for (int i = 0; i < PT; i++) {
        float y = (v[i] - mu) * inv * gm[lane + 32 * i] + bt[lane + 32 * i];
        Y[(size_t)row * D + lane + 32 * i] = __float2half_rn(fmaxf(y, 0.f));
    }
}

// ---------------- launch ----------------------------------------------------
extern "C" void kernel_launch(void* const* d_in, const int* in_sizes, int n_in,
                              void* d_out, int out_size) {
    const float* state = (const float*)d_in[0];
    const float* action = (const float*)d_in[1];
    const float* W1 = (const float*)d_in[2];
    const float* b1 = (const float*)d_in[3];
    const float* g1 = (const float*)d_in[4];
    const float* W2 = (const float*)d_in[5];
    const float* b2 = (const float*)d_in[6];
    const float* g2 = (const float*)d_in[7];
    const float* Wq1 = (const float*)d_in[8];
    const float* bq1 = (const float*)d_in[9];
    const float* ln1g = (const float*)d_in[10];
    const float* ln1b = (const float*)d_in[11];
    const float* Wq2 = (const float*)d_in[12];
    const float* bq2 = (const float*)d_in[13];
    const float* ln2g = (const float*)d_in[14];
    const float* ln2b = (const float*)d_in[15];
    const float* Wq3 = (const float*)d_in[16];
    const float* bq3 = (const float*)d_in[17];
    float* out = (float*)d_out;

    const int M = in_sizes[0] / 24;
    if (M <= 0) return;

    fp16 *saf, *w1t, *w2t, *q1t, *q2t, *x1f, *x2f, *h1f;
    float *h1p, *gt;
    cudaGetSymbolAddress((void**)&saf, g_SAf);
    cudaGetSymbolAddress((void**)&w1t, g_W1t);
    cudaGetSymbolAddress((void**)&w2t, g_W2t);
    cudaGetSymbolAddress((void**)&q1t, g_Q1t);
    cudaGetSymbolAddress((void**)&q2t, g_Q2t);
    cudaGetSymbolAddress((void**)&x1f, g_X1f);
    cudaGetSymbolAddress((void**)&x2f, g_X2f);
    cudaGetSymbolAddress((void**)&h1f, g_H1f);
    cudaGetSymbolAddress((void**)&h1p, g_H1p);
    cudaGetSymbolAddress((void**)&gt, g_GATE);

    const int SMEM_G = 2 * (2 * 128 * 64 * 2) + 1024;     // 66560 (3 CTAs/SM)
    const int SMEM_F = 128 * 132 * 4 + 1024;              // 68608 (3 CTAs/SM)
    cudaFuncSetAttribute(mma_gemm<0>, cudaFuncAttributeMaxDynamicSharedMemorySize, SMEM_G);
    cudaFuncSetAttribute(mma_gemm<1>, cudaFuncAttributeMaxDynamicSharedMemorySize, SMEM_G);
    cudaFuncSetAttribute(g3_fused, cudaFuncAttributeMaxDynamicSharedMemorySize, SMEM_F);

    prep_saf<<<(M * 64 + 255) / 256, 256>>>(state, action, saf, M);
    prep_w1t<<<(1024 * 64 + 255) / 256, 256>>>(W1, w1t);
    prep_w2t<<<(1024 * 1024 + 255) / 256, 256>>>(W2, w2t);
    prep_wt<<<(256 * 1024 + 255) / 256, 256>>>(Wq1, q1t, 256, 1024);
    prep_wt<<<(128 * 256 + 255) / 256, 256>>>(Wq2, q2t, 128, 256);
    prep_gates<<<1, 64>>>(g1, g2, gt);

    const int MB = M / 128;

    // G0: [M,64pad] @ [1024,64]^T -> X1 (tanh * gate1)
    mma_gemm<0><<<dim3(8, MB), 256, SMEM_G>>>(saf, w1t, 64, 1024, b1, gt, nullptr, x1f);
    // G1: [M,1024] @ [1024,1024]^T -> X2 (tanh * gate2)   (dominant)
    mma_gemm<0><<<dim3(8, MB), 256, SMEM_G>>>(x1f, w2t, 1024, 1024, b2, gt + 32, nullptr, x2f);
    // G2: [M,1024] @ [256,1024]^T -> H1p (+bq1)
    mma_gemm<1><<<dim3(2, MB), 256, SMEM_G>>>(x2f, q1t, 1024, 256, bq1, nullptr, h1p, nullptr);
    ln_relu_f16<256><<<(M + 7) / 8, 256>>>(h1p, ln1g, ln1b, h1f, M);
    // G3 fused: GEMM + LN2 + ReLU + dot -> out
    g3_fused<<<MB, 256, SMEM_F>>>(h1f, q2t, bq2, ln2g, ln2b, Wq3, bq3, out);
}

// round 15
// speedup vs baseline: 1.1951x; 1.0131x over previous
#include <cuda_runtime.h>
#include <cuda_fp16.h>
#include <math.h>
#include <stdint.h>

// ===========================================================================
// COR_Critic — single-pass fp16 mma.sync (HMMA) + ldmatrix + cp.async.
// R15 = R14 base (2-stage pipeline GEMM core + fused G3 tail)
//   + G0 runs only 2 k-steps (padded k 32..63 is exact zeros -> identical)
//   + all prep work merged into ONE kernel
//   + vectorized LN1 (float4 / uint4)
//   sa  = concat(state, action) -> [B,32] (padded to 64)
//   X1  = tanh(sa @ A1 + b1) * gate1      -> [B,1024]
//   X2  = tanh(X1 @ A2 + b2) * gate2      -> [B,1024]
//   H1p = X2 @ Wq1 + bq1 ; H1 = relu(LN(H1p))  (fp16)
//   out = relu(LN(H1 @ Wq2 + bq2)) @ Wq3 + bq3   (fused g3 kernel)
// ===========================================================================

#define NB 131072
using fp16 = __half;

// ---------------- device scratch (static, no allocation) -------------------
__device__ fp16 g_SAf[(size_t)NB * 64];
__device__ fp16 g_W1t[1024 * 64];
__device__ fp16 g_W2t[1024 * 1024];
__device__ fp16 g_Q1t[256 * 1024];
__device__ fp16 g_Q2t[128 * 256];
__device__ fp16 g_X1f[(size_t)NB * 1024];
__device__ fp16 g_X2f[(size_t)NB * 1024];
__device__ float g_H1p[(size_t)NB * 256];
__device__ fp16 g_H1f[(size_t)NB * 256];
__device__ float g_GATE[64];

// ---------------- PTX helpers ----------------------------------------------
__device__ __forceinline__ uint32_t smem_u32(const void* p) {
    uint32_t a;
    asm("{ .reg .u64 t; cvta.to.shared.u64 t, %1; cvt.u32.u64 %0, t; }"
        : "=r"(a) : "l"(p));
    return a;
}
__device__ __forceinline__ void cp16(uint32_t s, const void* g) {
    asm volatile("cp.async.cg.shared.global [%0], [%1], 16;" :: "r"(s), "l"(g));
}
#define CP_COMMIT() asm volatile("cp.async.commit_group;" ::: "memory")
__device__ __forceinline__ void ldsm4(uint32_t* r, uint32_t a) {
    asm volatile("ldmatrix.sync.aligned.m8n8.x4.shared.b16 {%0,%1,%2,%3}, [%4];"
                 : "=r"(r[0]), "=r"(r[1]), "=r"(r[2]), "=r"(r[3]) : "r"(a));
}
__device__ __forceinline__ void ldsm2(uint32_t* r, uint32_t a) {
    asm volatile("ldmatrix.sync.aligned.m8n8.x2.shared.b16 {%0,%1}, [%2];"
                 : "=r"(r[0]), "=r"(r[1]) : "r"(a));
}
__device__ __forceinline__ void mma16816(float* d, const uint32_t* a, const uint32_t* b) {
    asm volatile(
        "mma.sync.aligned.m16n8k16.row.col.f32.f16.f16.f32 "
        "{%0,%1,%2,%3}, {%4,%5,%6,%7}, {%8,%9}, {%0,%1,%2,%3};"
        : "+f"(d[0]), "+f"(d[1]), "+f"(d[2]), "+f"(d[3])
        : "r"(a[0]), "r"(a[1]), "r"(a[2]), "r"(a[3]), "r"(b[0]), "r"(b[1]));
}

// ---------------- merged prep kernel ---------------------------------------
// One launch handles: saf | w1t | w2t | q1t | q2t | gates (range dispatch).
__global__ void prep_all(const float* __restrict__ st, const float* __restrict__ ac,
                         const float* __restrict__ W1, const float* __restrict__ W2,
                         const float* __restrict__ Wq1, const float* __restrict__ Wq2,
                         const float* __restrict__ g1, const float* __restrict__ g2,
                         fp16* __restrict__ saf, fp16* __restrict__ w1t,
                         fp16* __restrict__ w2t, fp16* __restrict__ q1t,
                         fp16* __restrict__ q2t, float* __restrict__ gt, int M) {
    long long i = (long long)blockIdx.x * blockDim.x + threadIdx.x;
    const long long nSA = (long long)M * 64;
    if (i < nSA) {                                  // sa concat, zero-padded
        int b = (int)(i >> 6), j = (int)(i & 63);
        float v = 0.f;
        if (j < 24) v = st[b * 24 + j];
        else if (j < 32) v = ac[b * 8 + (j - 24)];
        saf[i] = __float2half_rn(v);
        return;
    }
    i -= nSA;
    if (i < 1024 * 64) {                            // W1t[n,k]=W1[n>>5,k,n&31]
        int n = (int)(i >> 6), k = (int)(i & 63);
        float v = (k < 32) ? W1[((size_t)((n >> 5) * 32 + k)) * 32 + (n & 31)] : 0.f;
        w1t[i] = __float2half_rn(v);
        return;
    }
    i -= 1024 * 64;
    if (i < 1024 * 1024) {                          // W2t[n,k]=W2[n>>5,k,n&31]
        int n = (int)(i >> 10), k = (int)(i & 1023);
        w2t[i] = __float2half_rn(W2[((size_t)(n >> 5) * 1024 + k) * 32 + (n & 31)]);
        return;
    }
    i -= 1024 * 1024;
    if (i < 256 * 1024) {                           // Q1t[n,k]=Wq1[k*256+n]
        int n = (int)(i >> 10), k = (int)(i & 1023);
        q1t[i] = __float2half_rn(Wq1[(size_t)k * 256 + n]);
        return;
    }
    i -= 256 * 1024;
    if (i < 128 * 256) {                            // Q2t[n,k]=Wq2[k*128+n]
        int n = (int)(i >> 8), k = (int)(i & 255);
        q2t[i] = __float2half_rn(Wq2[(size_t)k * 128 + n]);
        return;
    }
    i -= 128 * 256;
    if (i < 64) {                                   // sigmoid gates
        int t = (int)i;
        gt[t] = (t < 32) ? 1.0f / (1.0f + expf(-g1[t]))
                         : 1.0f / (1.0f + expf(-g2[t - 32]));
    }
}

// ---------------- HMMA GEMM (R8/R14-proven core) ----------------------------
// C[M,N] = Af[M,K] @ W[N,K]^T, fp32 acc in regs.
// BM=128, BN=128, BK=64, 8 warps (4m x 2n), warp tile 32x64, 2-stage.
// NKS: k-steps per tile actually computed (G0 uses 2: upper half is zeros).
// EPI 0: tanh(acc+bias)*gate -> fp16.   EPI 1: acc+bias -> fp32.
template <int EPI, int NKS>
__global__ void __launch_bounds__(256)
mma_gemm(const fp16* __restrict__ Af, const fp16* __restrict__ Bw,
         int K, int ldC,
         const float* __restrict__ bias, const float* __restrict__ gate,
         float* __restrict__ Cf, fp16* __restrict__ Ch) {
    constexpr int TILE = 128 * 64 * 2;   // 16 KB per operand tile
    constexpr int BUF = 2 * TILE;        // Af | Bw

    extern __shared__ char dsm[];
    const uint32_t sb = (smem_u32(dsm) + 1023) & ~1023u;

    const int tid = threadIdx.x;
    const int wid = tid >> 5, lane = tid & 31;
    const int wm = wid >> 1, wn = wid & 1;
    const size_t bm = (size_t)blockIdx.y * 128;
    const int bn = blockIdx.x * 128;
    const int nk = K >> 6;

    auto load_tile = [&](int kt, int buf) {
        const uint32_t base = sb + buf * BUF;
#pragma unroll
        for (int i = 0; i < 4; i++) {
            const int c = tid + 256 * i;
            const int row = c >> 3;
            const uint32_t sw = (uint32_t)(row * 128) +
                                (uint32_t)(((c & 7) << 4) ^ ((row & 7) << 4));
            const size_t kofs = (size_t)kt * 64 + ((c & 7) << 3);
            cp16(base + sw, Af + (bm + row) * (size_t)K + kofs);
            cp16(base + TILE + sw, Bw + (size_t)(bn + row) * K + kofs);
        }
    };

    const int r15 = lane & 15, halfA = lane >> 4;
    int pA[2], xA[2];
#pragma unroll
    for (int mt = 0; mt < 2; mt++) {
        const int rowA = wm * 32 + mt * 16 + r15;
        pA[mt] = rowA * 128;
        xA[mt] = (rowA & 7) << 4;
    }
    const int l8 = lane & 7, halfB = (lane & 15) >> 3;
    const int xB = l8 << 4;
    int pB[8];
#pragma unroll
    for (int nt = 0; nt < 8; nt++) pB[nt] = (wn * 64 + nt * 8 + l8) * 128;

    float acc[2][8][4];
#pragma unroll
    for (int mt = 0; mt < 2; mt++)
#pragma unroll
        for (int nt = 0; nt < 8; nt++)
#pragma unroll
            for (int q = 0; q < 4; q++) acc[mt][nt][q] = 0.f;

    load_tile(0, 0);
    CP_COMMIT();

    for (int kt = 0; kt < nk; kt++) {
        const int buf = kt & 1;
        if (kt + 1 < nk) {
            load_tile(kt + 1, buf ^ 1);
            CP_COMMIT();
            asm volatile("cp.async.wait_group 1;" ::: "memory");
        } else {
            asm volatile("cp.async.wait_group 0;" ::: "memory");
        }
        __syncthreads();

        const uint32_t tA = sb + buf * BUF;
        const uint32_t tB = tA + TILE;
#pragma unroll
        for (int ks = 0; ks < NKS; ks++) {
            const int kbA = ks * 32 + 16 * halfA;
            const int kbB = ks * 32 + 16 * halfB;
            uint32_t a[2][4], bfr[8][2];
#pragma unroll
            for (int mt = 0; mt < 2; mt++)
                ldsm4(a[mt], tA + pA[mt] + (kbA ^ xA[mt]));
#pragma unroll
            for (int nt = 0; nt < 8; nt++)
                ldsm2(bfr[nt], tB + pB[nt] + (kbB ^ xB));
#pragma unroll
            for (int mt = 0; mt < 2; mt++)
#pragma unroll
                for (int nt = 0; nt < 8; nt++)
                    mma16816(acc[mt][nt], a[mt], bfr[nt]);
        }
        __syncthreads();
    }

    const int gid = lane >> 2, qd = lane & 3;
#pragma unroll
    for (int nt = 0; nt < 8; nt++) {
        const int c = bn + wn * 64 + nt * 8 + qd * 2;
        const float b0 = bias[c], b1 = bias[c + 1];
        float gv = 0.f;
        if (EPI == 0) gv = gate[c >> 5];
#pragma unroll
        for (int mt = 0; mt < 2; mt++) {
            const size_t r0 = bm + wm * 32 + mt * 16 + gid;
            if (EPI == 0) {
#pragma unroll
                for (int half = 0; half < 2; half++) {
                    const size_t row = r0 + 8 * half;
                    const float v0 = tanhf(acc[mt][nt][2 * half + 0] + b0) * gv;
                    const float v1 = tanhf(acc[mt][nt][2 * half + 1] + b1) * gv;
                    *(uint32_t*)(Ch + row * (size_t)ldC + c) =
                        ((uint32_t)__half_as_ushort(__float2half_rn(v1)) << 16) |
                        __half_as_ushort(__float2half_rn(v0));
                }
            } else {
#pragma unroll
                for (int half = 0; half < 2; half++) {
                    const size_t row = r0 + 8 * half;
                    float2 o;
                    o.x = acc[mt][nt][2 * half + 0] + b0;
                    o.y = acc[mt][nt][2 * half + 1] + b1;
                    *(float2*)(Cf + row * (size_t)ldC + c) = o;
                }
            }
        }
    }
}

// ---------------- G3 fused: GEMM + LN2 + ReLU + dot -------------------------
__global__ void __launch_bounds__(256)
g3_fused(const fp16* __restrict__ Af, const fp16* __restrict__ Bw,
         const float* __restrict__ bq2,
         const float* __restrict__ ln2g, const float* __restrict__ ln2b,
         const float* __restrict__ wq3, const float* __restrict__ bq3,
         float* __restrict__ out) {
    constexpr int TILE = 128 * 64 * 2;
    constexpr int BUF = 2 * TILE;
    constexpr int K = 256, nk = 4;
    constexpr int PS = 132;             // fp32 row stride for pre-LN staging

    extern __shared__ char dsm[];
    const uint32_t sb = (smem_u32(dsm) + 1023) & ~1023u;

    const int tid = threadIdx.x;
    const int wid = tid >> 5, lane = tid & 31;
    const int wm = wid >> 1, wn = wid & 1;
    const size_t bm = (size_t)blockIdx.x * 128;

    auto load_tile = [&](int kt, int buf) {
        const uint32_t base = sb + buf * BUF;
#pragma unroll
        for (int i = 0; i < 4; i++) {
            const int c = tid + 256 * i;
            const int row = c >> 3;
            const uint32_t sw = (uint32_t)(row * 128) +
                                (uint32_t)(((c & 7) << 4) ^ ((row & 7) << 4));
            const size_t kofs = (size_t)kt * 64 + ((c & 7) << 3);
            cp16(base + sw, Af + (bm + row) * (size_t)K + kofs);
            cp16(base + TILE + sw, Bw + (size_t)row * K + kofs);
        }
    };

    const int r15 = lane & 15, halfA = lane >> 4;
    int pA[2], xA[2];
#pragma unroll
    for (int mt = 0; mt < 2; mt++) {
        const int rowA = wm * 32 + mt * 16 + r15;
        pA[mt] = rowA * 128;
        xA[mt] = (rowA & 7) << 4;
    }
    const int l8 = lane & 7, halfB = (lane & 15) >> 3;
    const int xB = l8 << 4;
    int pB[8];
#pragma unroll
    for (int nt = 0; nt < 8; nt++) pB[nt] = (wn * 64 + nt * 8 + l8) * 128;

    float acc[2][8][4];
#pragma unroll
    for (int mt = 0; mt < 2; mt++)
#pragma unroll
        for (int nt = 0; nt < 8; nt++)
#pragma unroll
            for (int q = 0; q < 4; q++) acc[mt][nt][q] = 0.f;

    load_tile(0, 0);
    CP_COMMIT();

    for (int kt = 0; kt < nk; kt++) {
        const int buf = kt & 1;
        if (kt + 1 < nk) {
            load_tile(kt + 1, buf ^ 1);
            CP_COMMIT();
            asm volatile("cp.async.wait_group 1;" ::: "memory");
        } else {
            asm volatile("cp.async.wait_group 0;" ::: "memory");
        }
        __syncthreads();

        const uint32_t tA = sb + buf * BUF;
        const uint32_t tB = tA + TILE;
#pragma unroll
        for (int ks = 0; ks < 4; ks++) {
            const int kbA = ks * 32 + 16 * halfA;
            const int kbB = ks * 32 + 16 * halfB;
            uint32_t a[2][4], bfr[8][2];
#pragma unroll
            for (int mt = 0; mt < 2; mt++)
                ldsm4(a[mt], tA + pA[mt] + (kbA ^ xA[mt]));
#pragma unroll
            for (int nt = 0; nt < 8; nt++)
                ldsm2(bfr[nt], tB + pB[nt] + (kbB ^ xB));
#pragma unroll
            for (int mt = 0; mt < 2; mt++)
#pragma unroll
                for (int nt = 0; nt < 8; nt++)
                    mma16816(acc[mt][nt], a[mt], bfr[nt]);
        }
        __syncthreads();   // also guards smem reuse by the staging below
    }

    // ---- stage pre-LN fp32 to SMEM ----
    float* const spre = (float*)(dsm + (sb - smem_u32(dsm)));
    const int gid = lane >> 2, qd = lane & 3;
#pragma unroll
    for (int nt = 0; nt < 8; nt++) {
        const int c = wn * 64 + nt * 8 + qd * 2;
        const float b0 = bq2[c], b1 = bq2[c + 1];
#pragma unroll
        for (int mt = 0; mt < 2; mt++) {
            const int r0 = wm * 32 + mt * 16 + gid;
#pragma unroll
            for (int half = 0; half < 2; half++) {
                const int row = r0 + 8 * half;
                spre[row * PS + c]     = acc[mt][nt][2 * half + 0] + b0;
                spre[row * PS + c + 1] = acc[mt][nt][2 * half + 1] + b1;
            }
        }
    }
    __syncthreads();

    // ---- LN2 + ReLU + dot(Wq3) -> out ----
    const float bq3v = bq3[0];
#pragma unroll
    for (int j = 0; j < 16; j++) {
        const int row = wid * 16 + j;
        float v[4];
        float s = 0.f;
#pragma unroll
        for (int i = 0; i < 4; i++) { v[i] = spre[row * PS + lane + 32 * i]; s += v[i]; }
#pragma unroll
        for (int o = 16; o; o >>= 1) s += __shfl_xor_sync(0xffffffffu, s, o);
        const float mu = s * (1.0f / 128.0f);
        float vs = 0.f;
#pragma unroll
        for (int i = 0; i < 4; i++) { float d = v[i] - mu; vs += d * d; }
#pragma unroll
        for (int o = 16; o; o >>= 1) vs += __shfl_xor_sync(0xffffffffu, vs, o);
        const float inv = rsqrtf(vs * (1.0f / 128.0f) + 1e-5f);
        float dot = 0.f;
#pragma unroll
        for (int i = 0; i < 4; i++) {
            const int c = lane + 32 * i;
            float y = (v[i] - mu) * inv * ln2g[c] + ln2b[c];
            y = fmaxf(y, 0.f);
            dot = fmaf(y, wq3[c], dot);
        }
#pragma unroll
        for (int o = 16; o; o >>= 1) dot += __shfl_xor_sync(0xffffffffu, dot, o);
        if (lane == 0) out[bm + row] = dot + bq3v;
    }
}

// ---------------- LN1 + ReLU -> fp16, vectorized (one warp per row) --------
// lane handles contiguous cols [lane*8, lane*8+8): float4 loads, uint4 store.
__global__ void ln_relu_f16_v(const float* __restrict__ X, const float* __restrict__ gm,
                              const float* __restrict__ bt, fp16* __restrict__ Y, int M) {
    const int row = blockIdx.x * (blockDim.x >> 5) + (threadIdx.x >> 5);
    if (row >= M) return;
    const int lane = threadIdx.x & 31;
    const float* rp = X + (size_t)row * 256 + lane * 8;
    float v[8];
    *(float4*)&v[0] = *(const float4*)(rp);
    *(float4*)&v[4] = *(const float4*)(rp + 4);
    float s = 0.f;
#pragma unroll
    for (int i = 0; i < 8; i++) s += v[i];
#pragma unroll
    for (int o = 16; o; o >>= 1) s += __shfl_xor_sync(0xffffffffu, s, o);
    const float mu = s * (1.0f / 256.0f);
    float vs = 0.f;
#pragma unroll
    for (int i = 0; i < 8; i++) { float d = v[i] - mu; vs += d * d; }
#pragma unroll
    for (int o = 16; o; o >>= 1) vs += __shfl_xor_sync(0xffffffffu, vs, o);
    const float inv = rsqrtf(vs * (1.0f / 256.0f) + 1e-5f);
    float g[8], b[8];
    *(float4*)&g[0] = *(const float4*)(gm + lane * 8);
    *(float4*)&g[4] = *(const float4*)(gm + lane * 8 + 4);
    *(float4*)&b[0] = *(const float4*)(bt + lane * 8);
    *(float4*)&b[4] = *(const float4*)(bt + lane * 8 + 4);
    uint32_t pk[4];
#pragma unroll
    for (int i = 0; i < 4; i++) {
        float y0 = fmaxf((v[2 * i]     - mu) * inv * g[2 * i]     + b[2 * i],     0.f);
        float y1 = fmaxf((v[2 * i + 1] - mu) * inv * g[2 * i + 1] + b[2 * i + 1], 0.f);
        pk[i] = ((uint32_t)__half_as_ushort(__float2half_rn(y1)) << 16) |
                __half_as_ushort(__float2half_rn(y0));
    }
    *(uint4*)(Y + (size_t)row * 256 + lane * 8) = *(uint4*)&pk[0];
}

// ---------------- launch ----------------------------------------------------
extern "C" void kernel_launch(void* const* d_in, const int* in_sizes, int n_in,
                              void* d_out, int out_size) {
    const float* state = (const float*)d_in[0];
    const float* action = (const float*)d_in[1];
    const float* W1 = (const float*)d_in[2];
    const float* b1 = (const float*)d_in[3];
    const float* g1 = (const float*)d_in[4];
    const float* W2 = (const float*)d_in[5];
    const float* b2 = (const float*)d_in[6];
    const float* g2 = (const float*)d_in[7];
    const float* Wq1 = (const float*)d_in[8];
    const float* bq1 = (const float*)d_in[9];
    const float* ln1g = (const float*)d_in[10];
    const float* ln1b = (const float*)d_in[11];
    const float* Wq2 = (const float*)d_in[12];
    const float* bq2 = (const float*)d_in[13];
    const float* ln2g = (const float*)d_in[14];
    const float* ln2b = (const float*)d_in[15];
    const float* Wq3 = (const float*)d_in[16];
    const float* bq3 = (const float*)d_in[17];
    float* out = (float*)d_out;

    const int M = in_sizes[0] / 24;
    if (M <= 0) return;

    fp16 *saf, *w1t, *w2t, *q1t, *q2t, *x1f, *x2f, *h1f;
    float *h1p, *gt;
    cudaGetSymbolAddress((void**)&saf, g_SAf);
    cudaGetSymbolAddress((void**)&w1t, g_W1t);
    cudaGetSymbolAddress((void**)&w2t, g_W2t);
    cudaGetSymbolAddress((void**)&q1t, g_Q1t);
    cudaGetSymbolAddress((void**)&q2t, g_Q2t);
    cudaGetSymbolAddress((void**)&x1f, g_X1f);
    cudaGetSymbolAddress((void**)&x2f, g_X2f);
    cudaGetSymbolAddress((void**)&h1f, g_H1f);
    cudaGetSymbolAddress((void**)&h1p, g_H1p);
    cudaGetSymbolAddress((void**)&gt, g_GATE);

    const int SMEM_G = 2 * (2 * 128 * 64 * 2) + 1024;     // 66560
    const int SMEM_F = 128 * 132 * 4 + 1024;              // 68608
    cudaFuncSetAttribute(mma_gemm<0, 2>, cudaFuncAttributeMaxDynamicSharedMemorySize, SMEM_G);
    cudaFuncSetAttribute(mma_gemm<0, 4>, cudaFuncAttributeMaxDynamicSharedMemorySize, SMEM_G);
    cudaFuncSetAttribute(mma_gemm<1, 4>, cudaFuncAttributeMaxDynamicSharedMemorySize, SMEM_G);
    cudaFuncSetAttribute(g3_fused, cudaFuncAttributeMaxDynamicSharedMemorySize, SMEM_F);

    // merged prep: saf | w1t | w2t | q1t | q2t | gates
    const long long nPrep = (long long)M * 64 + 1024 * 64 + 1024 * 1024 +
                            256 * 1024 + 128 * 256 + 64;
    prep_all<<<(int)((nPrep + 255) / 256), 256>>>(state, action, W1, W2, Wq1, Wq2,
                                                  g1, g2, saf, w1t, w2t, q1t, q2t,
                                                  gt, M);

    const int MB = M / 128;

    // G0: [M,64pad] @ [1024,64]^T -> X1 (tanh*gate1); k 32..63 are exact zeros
    mma_gemm<0, 2><<<dim3(8, MB), 256, SMEM_G>>>(saf, w1t, 64, 1024, b1, gt, nullptr, x1f);
    // G1: [M,1024] @ [1024,1024]^T -> X2 (tanh * gate2)   (dominant)
    mma_gemm<0, 4><<<dim3(8, MB), 256, SMEM_G>>>(x1f, w2t, 1024, 1024, b2, gt + 32, nullptr, x2f);
    // G2: [M,1024] @ [256,1024]^T -> H1p (+bq1)
    mma_gemm<1, 4><<<dim3(2, MB), 256, SMEM_G>>>(x2f, q1t, 1024, 256, bq1, nullptr, h1p, nullptr);
    ln_relu_f16_v<<<(M + 7) / 8, 256>>>(h1p, ln1g, ln1b, h1f, M);
    // G3 fused: GEMM + LN2 + ReLU + dot -> out
    g3_fused<<<MB, 256, SMEM_F>>>(h1f, q2t, bq2, ln2g, ln2b, Wq3, bq3, out);
}